// round 11
// baseline (speedup 1.0000x reference)
#include <cuda_runtime.h>
#include <stdint.h>

// UniformAggregationPure: hyperedge mean aggregation via counting-sort CSR.
//   out[he, :] = mean over edges e with he_idx[e]==he of node_feats[node_idx[e], :]
//
// Pipeline (all scratch in __device__ globals; no allocations):
//   detect  : int32 vs int64 index dtype (JAX may silently downcast)
//   zmeta   : zero per-he counts
//   count   : histogram edges per hyperedge
//   scan x3 : exclusive scan counts -> offsets (also zeros cursors)
//   permute : node ids grouped by hyperedge (CSR)
//   agg     : warp per he, register accumulation, fused divide, single store
// Fallback (shapes too big for scratch): zero + red.v4 scatter + divide.

#define HIDDEN    128
#define MAX_HE    65536
#define MAX_EDGES (1 << 20)
#define SCAN_CHUNK 8192          // 1024 threads x 8 elems
#define MAX_SCAN_BLOCKS 64

__device__ int   g_is64;
__device__ int   g_counts_i[MAX_HE];
__device__ int   g_offsets[MAX_HE + 1];
__device__ int   g_cursor[MAX_HE];
__device__ int   g_sorted_node[MAX_EDGES];
__device__ int   g_blocksums[MAX_SCAN_BLOCKS];
__device__ float g_counts_f[MAX_HE];   // fallback path only

// ---------------- dtype detection ------------------------------------------
__global__ void detect_kernel(const int* __restrict__ raw, int n_words) {
    int lane = threadIdx.x;
    int all_zero = 1;
    for (int i = lane * 2 + 1; i < 256 && i < n_words; i += 64)
        if (raw[i] != 0) all_zero = 0;
    all_zero = __all_sync(0xFFFFFFFF, all_zero);
    if (lane == 0) g_is64 = all_zero;
}

__device__ __forceinline__ void load_edge(const void* idx_raw, int e, int n_edges,
                                          int& node, int& he) {
    if (g_is64) {
        const long long* p = (const long long*)idx_raw;
        node = (int)__ldg(&p[e]);
        he   = (int)__ldg(&p[n_edges + e]);
    } else {
        const int* p = (const int*)idx_raw;
        node = __ldg(&p[e]);
        he   = __ldg(&p[n_edges + e]);
    }
}

// ---------------- CSR build -------------------------------------------------
__global__ void zmeta_kernel(int num_he) {
    int i = blockIdx.x * blockDim.x + threadIdx.x;
    int stride = gridDim.x * blockDim.x;
    for (int j = i; j < num_he; j += stride) g_counts_i[j] = 0;
}

__global__ void __launch_bounds__(256) count_kernel(
    const void* __restrict__ idx_raw, int n_edges, int n_nodes, int num_he) {
    int i = blockIdx.x * blockDim.x + threadIdx.x;
    int stride = gridDim.x * blockDim.x;
    for (int e = i; e < n_edges; e += stride) {
        int node, he;
        load_edge(idx_raw, e, n_edges, node, he);
        if ((unsigned)node < (unsigned)n_nodes && (unsigned)he < (unsigned)num_he)
            atomicAdd(&g_counts_i[he], 1);
    }
}

// scan pass 1: per-chunk sums
__global__ void __launch_bounds__(1024) scan_reduce_kernel(int num_he) {
    int base = blockIdx.x * SCAN_CHUNK;
    int t = threadIdx.x;
    int s = 0;
    for (int i = t; i < SCAN_CHUNK; i += 1024) {
        int g = base + i;
        if (g < num_he) s += g_counts_i[g];
    }
    // warp + block reduce
    for (int o = 16; o > 0; o >>= 1) s += __shfl_down_sync(0xFFFFFFFF, s, o);
    __shared__ int wsum[32];
    if ((t & 31) == 0) wsum[t >> 5] = s;
    __syncthreads();
    if (t < 32) {
        int v = wsum[t];
        for (int o = 16; o > 0; o >>= 1) v += __shfl_down_sync(0xFFFFFFFF, v, o);
        if (t == 0) g_blocksums[blockIdx.x] = v;
    }
}

// scan pass 2: exclusive scan of block sums (serial; NB <= 64) + total
__global__ void scan_top_kernel(int nb, int num_he) {
    if (threadIdx.x == 0) {
        int run = 0;
        for (int b = 0; b < nb; b++) {
            int v = g_blocksums[b];
            g_blocksums[b] = run;
            run += v;
        }
        g_offsets[num_he] = run;
    }
}

// scan pass 3: full exclusive scan within chunk, write offsets, zero cursors
__global__ void __launch_bounds__(1024) scan_final_kernel(int num_he) {
    int base = blockIdx.x * SCAN_CHUNK;
    int t = threadIdx.x;
    int idx0 = base + t * 8;
    int vals[8];
    int tot = 0;
#pragma unroll
    for (int i = 0; i < 8; i++) {
        int g = idx0 + i;
        vals[i] = (g < num_he) ? g_counts_i[g] : 0;
        tot += vals[i];
    }
    // inclusive warp scan of thread totals
    int lane = t & 31, w = t >> 5;
    int inc = tot;
    for (int o = 1; o < 32; o <<= 1) {
        int n = __shfl_up_sync(0xFFFFFFFF, inc, o);
        if (lane >= o) inc += n;
    }
    __shared__ int wsum[32];
    if (lane == 31) wsum[w] = inc;
    __syncthreads();
    if (w == 0) {
        int v = wsum[lane];
        for (int o = 1; o < 32; o <<= 1) {
            int n = __shfl_up_sync(0xFFFFFFFF, v, o);
            if (lane >= o) v += n;
        }
        wsum[lane] = v;
    }
    __syncthreads();
    int excl = inc - tot + (w > 0 ? wsum[w - 1] : 0) + g_blocksums[blockIdx.x];
    int run = excl;
#pragma unroll
    for (int i = 0; i < 8; i++) {
        int g = idx0 + i;
        if (g < num_he) { g_offsets[g] = run; g_cursor[g] = 0; }
        run += vals[i];
    }
}

__global__ void __launch_bounds__(256) permute_kernel(
    const void* __restrict__ idx_raw, int n_edges, int n_nodes, int num_he) {
    int i = blockIdx.x * blockDim.x + threadIdx.x;
    int stride = gridDim.x * blockDim.x;
    for (int e = i; e < n_edges; e += stride) {
        int node, he;
        load_edge(idx_raw, e, n_edges, node, he);
        if ((unsigned)node < (unsigned)n_nodes && (unsigned)he < (unsigned)num_he) {
            int pos = g_offsets[he] + atomicAdd(&g_cursor[he], 1);
            g_sorted_node[pos] = node;
        }
    }
}

// ---------------- aggregation: warp per hyperedge ---------------------------
__global__ void __launch_bounds__(256) aggregate_kernel(
    const float* __restrict__ feats, float* __restrict__ out, int num_he) {
    int warp = (blockIdx.x * blockDim.x + threadIdx.x) >> 5;
    int lane = threadIdx.x & 31;
    if (warp >= num_he) return;

    int beg = g_offsets[warp];
    int end = g_offsets[warp + 1];

    float4 acc = make_float4(0.f, 0.f, 0.f, 0.f);
    for (int c = beg; c < end; c += 32) {
        int n = end - c;
        if (n > 32) n = 32;
        int myid = (lane < n) ? __ldg(&g_sorted_node[c + lane]) : 0;  // coalesced
#pragma unroll 4
        for (int k = 0; k < n; k++) {
            int node = __shfl_sync(0xFFFFFFFF, myid, k);
            float4 v = __ldg(reinterpret_cast<const float4*>(
                                 feats + (long long)node * HIDDEN) + lane);
            acc.x += v.x; acc.y += v.y; acc.z += v.z; acc.w += v.w;
        }
    }
    float inv = 1.0f / fmaxf((float)(end - beg), 1.0f);
    acc.x *= inv; acc.y *= inv; acc.z *= inv; acc.w *= inv;
    reinterpret_cast<float4*>(out)[(long long)warp * 32 + lane] = acc;
}

// ---------------- fallback path (round-5 proven) -----------------------------
__global__ void zero_kernel(float4* __restrict__ out4, int n4, int num_he) {
    int stride = gridDim.x * blockDim.x;
    int i = blockIdx.x * blockDim.x + threadIdx.x;
    const float4 z = make_float4(0.f, 0.f, 0.f, 0.f);
    for (int j = i; j < n4; j += stride) out4[j] = z;
    for (int j = i; j < num_he && j < MAX_HE; j += stride) g_counts_f[j] = 0.f;
}

__global__ void __launch_bounds__(256) scatter_kernel(
    const float* __restrict__ feats, const void* __restrict__ idx_raw,
    float* __restrict__ out, int n_edges, int n_nodes, int num_he) {
    int warp = (blockIdx.x * blockDim.x + threadIdx.x) >> 5;
    int lane = threadIdx.x & 31;
    if (warp >= n_edges) return;
    int node, he;
    load_edge(idx_raw, warp, n_edges, node, he);
    if ((unsigned)node >= (unsigned)n_nodes || (unsigned)he >= (unsigned)num_he)
        return;
    float4 v = __ldg(reinterpret_cast<const float4*>(
                         feats + (long long)node * HIDDEN) + lane);
    float* dst = out + (long long)he * HIDDEN + lane * 4;
    asm volatile("red.global.add.v4.f32 [%0], {%1, %2, %3, %4};"
                 :: "l"(dst), "f"(v.x), "f"(v.y), "f"(v.z), "f"(v.w) : "memory");
    if (lane == 0 && he < MAX_HE) atomicAdd(&g_counts_f[he], 1.0f);
}

__global__ void __launch_bounds__(HIDDEN) divide_kernel(float* __restrict__ out) {
    int he = blockIdx.x;
    float inv = 1.0f / fmaxf(g_counts_f[he], 1.0f);
    out[(long long)he * HIDDEN + threadIdx.x] *= inv;
}

// ---------------- launch -----------------------------------------------------
extern "C" void kernel_launch(void* const* d_in, const int* in_sizes, int n_in,
                              void* d_out, int out_size) {
    const float* feats = (const float*)d_in[0];
    const void*  idx   = d_in[1];
    int n_edges = in_sizes[1] / 2;
    int n_nodes = in_sizes[0] / HIDDEN;
    float* out = (float*)d_out;
    int num_he = out_size / HIDDEN;

    detect_kernel<<<1, 32>>>((const int*)idx, in_sizes[1]);

    int nb_scan = (num_he + SCAN_CHUNK - 1) / SCAN_CHUNK;

    if (n_edges <= MAX_EDGES && num_he <= MAX_HE && nb_scan <= MAX_SCAN_BLOCKS) {
        // CSR path
        zmeta_kernel<<<(num_he + 1023) / 1024, 1024>>>(num_he);

        int blk_e = (n_edges + 255) / 256;
        if (blk_e > 2048) blk_e = 2048;
        count_kernel<<<blk_e, 256>>>(idx, n_edges, n_nodes, num_he);

        scan_reduce_kernel<<<nb_scan, 1024>>>(num_he);
        scan_top_kernel<<<1, 32>>>(nb_scan, num_he);
        scan_final_kernel<<<nb_scan, 1024>>>(num_he);

        permute_kernel<<<blk_e, 256>>>(idx, n_edges, n_nodes, num_he);

        int warps = num_he;
        int blocks = (warps * 32 + 255) / 256;
        aggregate_kernel<<<blocks, 256>>>(feats, out, num_he);
    } else {
        // fallback: proven scatter path
        int n4 = out_size / 4;
        int zb = (n4 + 255) / 256;
        if (zb > 4096) zb = 4096;
        zero_kernel<<<zb, 256>>>((float4*)out, n4, num_he);
        long long total_threads = (long long)n_edges * 32;
        scatter_kernel<<<(int)((total_threads + 255) / 256), 256>>>(
            feats, idx, out, n_edges, n_nodes, num_he);
        divide_kernel<<<num_he, HIDDEN>>>(out);
    }
}

// round 12
// speedup vs baseline: 1.0075x; 1.0075x over previous
#include <cuda_runtime.h>
#include <stdint.h>

// UniformAggregationPure: hyperedge mean aggregation via counting-sort CSR.
//   out[he, :] = mean over edges e with he_idx[e]==he of node_feats[node_idx[e], :]
//
// Pipeline (all scratch in __device__ globals; no allocations):
//   detect  : int32 vs int64 index dtype (JAX may silently downcast)
//   zmeta   : zero per-he counts
//   count   : histogram edges per hyperedge
//   scan x3 : exclusive scan counts -> offsets (also zeros cursors)
//   permute : node ids grouped by hyperedge (CSR)
//   agg     : warp per he, register accumulation, fused divide, single store
// Fallback (shapes too big for scratch): zero + red.v4 scatter + divide.

#define HIDDEN    128
#define MAX_HE    65536
#define MAX_EDGES (1 << 20)
#define SCAN_CHUNK 8192          // 1024 threads x 8 elems
#define MAX_SCAN_BLOCKS 64

__device__ int   g_is64;
__device__ int   g_counts_i[MAX_HE];
__device__ int   g_offsets[MAX_HE + 1];
__device__ int   g_cursor[MAX_HE];
__device__ int   g_sorted_node[MAX_EDGES];
__device__ int   g_blocksums[MAX_SCAN_BLOCKS];
__device__ float g_counts_f[MAX_HE];   // fallback path only

// ---------------- dtype detection ------------------------------------------
__global__ void detect_kernel(const int* __restrict__ raw, int n_words) {
    int lane = threadIdx.x;
    int all_zero = 1;
    for (int i = lane * 2 + 1; i < 256 && i < n_words; i += 64)
        if (raw[i] != 0) all_zero = 0;
    all_zero = __all_sync(0xFFFFFFFF, all_zero);
    if (lane == 0) g_is64 = all_zero;
}

__device__ __forceinline__ void load_edge(const void* idx_raw, int e, int n_edges,
                                          int& node, int& he) {
    if (g_is64) {
        const long long* p = (const long long*)idx_raw;
        node = (int)__ldg(&p[e]);
        he   = (int)__ldg(&p[n_edges + e]);
    } else {
        const int* p = (const int*)idx_raw;
        node = __ldg(&p[e]);
        he   = __ldg(&p[n_edges + e]);
    }
}

// ---------------- CSR build -------------------------------------------------
__global__ void zmeta_kernel(int num_he) {
    int i = blockIdx.x * blockDim.x + threadIdx.x;
    int stride = gridDim.x * blockDim.x;
    for (int j = i; j < num_he; j += stride) g_counts_i[j] = 0;
}

__global__ void __launch_bounds__(256) count_kernel(
    const void* __restrict__ idx_raw, int n_edges, int n_nodes, int num_he) {
    int i = blockIdx.x * blockDim.x + threadIdx.x;
    int stride = gridDim.x * blockDim.x;
    for (int e = i; e < n_edges; e += stride) {
        int node, he;
        load_edge(idx_raw, e, n_edges, node, he);
        if ((unsigned)node < (unsigned)n_nodes && (unsigned)he < (unsigned)num_he)
            atomicAdd(&g_counts_i[he], 1);
    }
}

// scan pass 1: per-chunk sums
__global__ void __launch_bounds__(1024) scan_reduce_kernel(int num_he) {
    int base = blockIdx.x * SCAN_CHUNK;
    int t = threadIdx.x;
    int s = 0;
    for (int i = t; i < SCAN_CHUNK; i += 1024) {
        int g = base + i;
        if (g < num_he) s += g_counts_i[g];
    }
    // warp + block reduce
    for (int o = 16; o > 0; o >>= 1) s += __shfl_down_sync(0xFFFFFFFF, s, o);
    __shared__ int wsum[32];
    if ((t & 31) == 0) wsum[t >> 5] = s;
    __syncthreads();
    if (t < 32) {
        int v = wsum[t];
        for (int o = 16; o > 0; o >>= 1) v += __shfl_down_sync(0xFFFFFFFF, v, o);
        if (t == 0) g_blocksums[blockIdx.x] = v;
    }
}

// scan pass 2: exclusive scan of block sums (serial; NB <= 64) + total
__global__ void scan_top_kernel(int nb, int num_he) {
    if (threadIdx.x == 0) {
        int run = 0;
        for (int b = 0; b < nb; b++) {
            int v = g_blocksums[b];
            g_blocksums[b] = run;
            run += v;
        }
        g_offsets[num_he] = run;
    }
}

// scan pass 3: full exclusive scan within chunk, write offsets, zero cursors
__global__ void __launch_bounds__(1024) scan_final_kernel(int num_he) {
    int base = blockIdx.x * SCAN_CHUNK;
    int t = threadIdx.x;
    int idx0 = base + t * 8;
    int vals[8];
    int tot = 0;
#pragma unroll
    for (int i = 0; i < 8; i++) {
        int g = idx0 + i;
        vals[i] = (g < num_he) ? g_counts_i[g] : 0;
        tot += vals[i];
    }
    // inclusive warp scan of thread totals
    int lane = t & 31, w = t >> 5;
    int inc = tot;
    for (int o = 1; o < 32; o <<= 1) {
        int n = __shfl_up_sync(0xFFFFFFFF, inc, o);
        if (lane >= o) inc += n;
    }
    __shared__ int wsum[32];
    if (lane == 31) wsum[w] = inc;
    __syncthreads();
    if (w == 0) {
        int v = wsum[lane];
        for (int o = 1; o < 32; o <<= 1) {
            int n = __shfl_up_sync(0xFFFFFFFF, v, o);
            if (lane >= o) v += n;
        }
        wsum[lane] = v;
    }
    __syncthreads();
    int excl = inc - tot + (w > 0 ? wsum[w - 1] : 0) + g_blocksums[blockIdx.x];
    int run = excl;
#pragma unroll
    for (int i = 0; i < 8; i++) {
        int g = idx0 + i;
        if (g < num_he) { g_offsets[g] = run; g_cursor[g] = 0; }
        run += vals[i];
    }
}

__global__ void __launch_bounds__(256) permute_kernel(
    const void* __restrict__ idx_raw, int n_edges, int n_nodes, int num_he) {
    int i = blockIdx.x * blockDim.x + threadIdx.x;
    int stride = gridDim.x * blockDim.x;
    for (int e = i; e < n_edges; e += stride) {
        int node, he;
        load_edge(idx_raw, e, n_edges, node, he);
        if ((unsigned)node < (unsigned)n_nodes && (unsigned)he < (unsigned)num_he) {
            int pos = g_offsets[he] + atomicAdd(&g_cursor[he], 1);
            g_sorted_node[pos] = node;
        }
    }
}

// ---------------- aggregation: warp per hyperedge ---------------------------
__global__ void __launch_bounds__(256) aggregate_kernel(
    const float* __restrict__ feats, float* __restrict__ out, int num_he) {
    int warp = (blockIdx.x * blockDim.x + threadIdx.x) >> 5;
    int lane = threadIdx.x & 31;
    if (warp >= num_he) return;

    int beg = g_offsets[warp];
    int end = g_offsets[warp + 1];

    float4 acc = make_float4(0.f, 0.f, 0.f, 0.f);
    for (int c = beg; c < end; c += 32) {
        int n = end - c;
        if (n > 32) n = 32;
        int myid = (lane < n) ? __ldg(&g_sorted_node[c + lane]) : 0;  // coalesced
#pragma unroll 4
        for (int k = 0; k < n; k++) {
            int node = __shfl_sync(0xFFFFFFFF, myid, k);
            float4 v = __ldg(reinterpret_cast<const float4*>(
                                 feats + (long long)node * HIDDEN) + lane);
            acc.x += v.x; acc.y += v.y; acc.z += v.z; acc.w += v.w;
        }
    }
    float inv = 1.0f / fmaxf((float)(end - beg), 1.0f);
    acc.x *= inv; acc.y *= inv; acc.z *= inv; acc.w *= inv;
    reinterpret_cast<float4*>(out)[(long long)warp * 32 + lane] = acc;
}

// ---------------- fallback path (round-5 proven) -----------------------------
__global__ void zero_kernel(float4* __restrict__ out4, int n4, int num_he) {
    int stride = gridDim.x * blockDim.x;
    int i = blockIdx.x * blockDim.x + threadIdx.x;
    const float4 z = make_float4(0.f, 0.f, 0.f, 0.f);
    for (int j = i; j < n4; j += stride) out4[j] = z;
    for (int j = i; j < num_he && j < MAX_HE; j += stride) g_counts_f[j] = 0.f;
}

__global__ void __launch_bounds__(256) scatter_kernel(
    const float* __restrict__ feats, const void* __restrict__ idx_raw,
    float* __restrict__ out, int n_edges, int n_nodes, int num_he) {
    int warp = (blockIdx.x * blockDim.x + threadIdx.x) >> 5;
    int lane = threadIdx.x & 31;
    if (warp >= n_edges) return;
    int node, he;
    load_edge(idx_raw, warp, n_edges, node, he);
    if ((unsigned)node >= (unsigned)n_nodes || (unsigned)he >= (unsigned)num_he)
        return;
    float4 v = __ldg(reinterpret_cast<const float4*>(
                         feats + (long long)node * HIDDEN) + lane);
    float* dst = out + (long long)he * HIDDEN + lane * 4;
    asm volatile("red.global.add.v4.f32 [%0], {%1, %2, %3, %4};"
                 :: "l"(dst), "f"(v.x), "f"(v.y), "f"(v.z), "f"(v.w) : "memory");
    if (lane == 0 && he < MAX_HE) atomicAdd(&g_counts_f[he], 1.0f);
}

__global__ void __launch_bounds__(HIDDEN) divide_kernel(float* __restrict__ out) {
    int he = blockIdx.x;
    float inv = 1.0f / fmaxf(g_counts_f[he], 1.0f);
    out[(long long)he * HIDDEN + threadIdx.x] *= inv;
}

// ---------------- launch -----------------------------------------------------
extern "C" void kernel_launch(void* const* d_in, const int* in_sizes, int n_in,
                              void* d_out, int out_size) {
    const float* feats = (const float*)d_in[0];
    const void*  idx   = d_in[1];
    int n_edges = in_sizes[1] / 2;
    int n_nodes = in_sizes[0] / HIDDEN;
    float* out = (float*)d_out;
    int num_he = out_size / HIDDEN;

    detect_kernel<<<1, 32>>>((const int*)idx, in_sizes[1]);

    int nb_scan = (num_he + SCAN_CHUNK - 1) / SCAN_CHUNK;

    if (n_edges <= MAX_EDGES && num_he <= MAX_HE && nb_scan <= MAX_SCAN_BLOCKS) {
        // CSR path
        zmeta_kernel<<<(num_he + 1023) / 1024, 1024>>>(num_he);

        int blk_e = (n_edges + 255) / 256;
        if (blk_e > 2048) blk_e = 2048;
        count_kernel<<<blk_e, 256>>>(idx, n_edges, n_nodes, num_he);

        scan_reduce_kernel<<<nb_scan, 1024>>>(num_he);
        scan_top_kernel<<<1, 32>>>(nb_scan, num_he);
        scan_final_kernel<<<nb_scan, 1024>>>(num_he);

        permute_kernel<<<blk_e, 256>>>(idx, n_edges, n_nodes, num_he);

        int warps = num_he;
        int blocks = (warps * 32 + 255) / 256;
        aggregate_kernel<<<blocks, 256>>>(feats, out, num_he);
    } else {
        // fallback: proven scatter path
        int n4 = out_size / 4;
        int zb = (n4 + 255) / 256;
        if (zb > 4096) zb = 4096;
        zero_kernel<<<zb, 256>>>((float4*)out, n4, num_he);
        long long total_threads = (long long)n_edges * 32;
        scatter_kernel<<<(int)((total_threads + 255) / 256), 256>>>(
            feats, idx, out, n_edges, n_nodes, num_he);
        divide_kernel<<<num_he, HIDDEN>>>(out);
    }
}